// round 7
// baseline (speedup 1.0000x reference)
#include <cuda_runtime.h>

// RouterModel: N=32768 tokens, D=1024, P=2 paths.
// d = x . (W[:,0]-W[:,1]); path = d>=0 ? 0 : 1; gate = sigmoid(|d|)
// out = [x0 | x1 | xc], each [N, D] float32.
//
// Warp-per-token layout: 8 warps/block, each warp owns one token.
// Each thread front-batches 8 LDG.128 (MLP=8), warp-shfl reduce only
// (no block barrier in the hot path), then 24 STG.128.
// wdiff = W[:,0]-W[:,1] staged once per block in 4KB smem.

#define N_TOK   32768
#define DHID    1024
#define ROW4    (DHID / 4)      // 256 float4 per row
#define THREADS 256
#define WARPS   (THREADS / 32)  // 8 tokens per block

__global__ __launch_bounds__(THREADS) void router_kernel(
    const float* __restrict__ x, const float* __restrict__ W,
    float* __restrict__ out)
{
    __shared__ float4 swd[ROW4];   // wdiff, 1024 floats = 4 KB

    const int t = threadIdx.x;

    // One-time cooperative wdiff: thread t covers floats 4t..4t+3.
    // W layout [D,2] row-major: (W0,W1) pairs interleaved.
    {
        const float4 wa = __ldg(reinterpret_cast<const float4*>(W) + 2 * t);
        const float4 wb = __ldg(reinterpret_cast<const float4*>(W) + 2 * t + 1);
        swd[t] = make_float4(wa.x - wa.y, wa.z - wa.w, wb.x - wb.y, wb.z - wb.w);
    }
    __syncthreads();   // only barrier; outside the streaming path

    const int warp = t >> 5, lane = t & 31;
    const int n = blockIdx.x * WARPS + warp;

    // Front-batched row load: 8 independent LDG.128 per thread.
    const float4* xr = reinterpret_cast<const float4*>(x + (size_t)n * DHID);
    float4 v[8];
    #pragma unroll
    for (int r = 0; r < 8; r++)
        v[r] = xr[lane + 32 * r];

    // Dot with wdiff from smem (conflict-free LDS.128).
    float p = 0.0f;
    #pragma unroll
    for (int r = 0; r < 8; r++) {
        const float4 w = swd[lane + 32 * r];
        p += v[r].x * w.x + v[r].y * w.y + v[r].z * w.z + v[r].w * w.w;
    }

    // Warp-only reduction.
    #pragma unroll
    for (int o = 16; o > 0; o >>= 1)
        p += __shfl_xor_sync(0xffffffffu, p, o);

    // gate = softmax max-prob = sigmoid(|d|); path 0 iff d >= 0 (argmax tie -> 0)
    const float g = 1.0f / (1.0f + expf(-fabsf(p)));
    const bool  path0 = (p >= 0.0f);

    const size_t row4  = (size_t)n * ROW4 + lane;
    const size_t sect4 = (size_t)N_TOK * ROW4;
    float4* o4 = reinterpret_cast<float4*>(out);
    const float4 zero = make_float4(0.f, 0.f, 0.f, 0.f);

    // x0 section
    #pragma unroll
    for (int r = 0; r < 8; r++) {
        const float4 sv = make_float4(v[r].x * g, v[r].y * g, v[r].z * g, v[r].w * g);
        o4[row4 + 32 * r] = path0 ? sv : zero;
    }
    // x1 section
    #pragma unroll
    for (int r = 0; r < 8; r++) {
        const float4 sv = make_float4(v[r].x * g, v[r].y * g, v[r].z * g, v[r].w * g);
        o4[sect4 + row4 + 32 * r] = path0 ? zero : sv;
    }
    // xc section
    #pragma unroll
    for (int r = 0; r < 8; r++) {
        const float4 sv = make_float4(v[r].x * g, v[r].y * g, v[r].z * g, v[r].w * g);
        o4[2 * sect4 + row4 + 32 * r] = sv;
    }
}

extern "C" void kernel_launch(void* const* d_in, const int* in_sizes, int n_in,
                              void* d_out, int out_size) {
    const float* x = (const float*)d_in[0];   // [N, D] float32
    const float* W = (const float*)d_in[1];   // [D, 2] float32
    float* out = (float*)d_out;               // [3, N, D] float32

    router_kernel<<<N_TOK / WARPS, THREADS>>>(x, W, out);
}

// round 8
// speedup vs baseline: 1.0023x; 1.0023x over previous
#include <cuda_runtime.h>

// RouterModel: N=32768 tokens, D=1024, P=2 paths.
// d = x . (W[:,0]-W[:,1]); path = d>=0 ? 0 : 1; gate = sigmoid(|d|)
// out = [x0 | x1 | xc], each [N, D] float32.
//
// Single fused kernel, block-per-token (measured-best structure, R3):
// 256 threads x 1 float4 each, high occupancy hides DRAM latency.
// Plain cache ops (streaming hints measured negative in R4).
// W is 8KB -> L1-resident; per-thread column-diff fold, no extra launch.

#define N_TOK   32768
#define DHID    1024
#define THREADS 256   // DHID/4 float4 lanes per row

__global__ __launch_bounds__(THREADS) void router_kernel(
    const float* __restrict__ x, const float* __restrict__ W,
    float* __restrict__ out)
{
    const int n = blockIdx.x;
    const int t = threadIdx.x;

    // This thread's float4 slice of the token row (plain LDG.128).
    const float4 v = reinterpret_cast<const float4*>(x + (size_t)n * DHID)[t];

    // W rows 4t..4t+3, layout [D,2] row-major: (W0,W1) pairs interleaved.
    // 2 LDG.128, L1-hit after the first CTA on each SM.
    const float4 wa = reinterpret_cast<const float4*>(W)[2 * t];
    const float4 wb = reinterpret_cast<const float4*>(W)[2 * t + 1];

    // Partial dot with (W0 - W1), folded in registers.
    float p = v.x * (wa.x - wa.y) + v.y * (wa.z - wa.w)
            + v.z * (wb.x - wb.y) + v.w * (wb.z - wb.w);

    // Warp reduce.
    #pragma unroll
    for (int o = 16; o > 0; o >>= 1)
        p += __shfl_xor_sync(0xffffffffu, p, o);

    __shared__ float s[THREADS / 32];
    const int wid = t >> 5, lid = t & 31;
    if (lid == 0) s[wid] = p;
    __syncthreads();

    float d = 0.0f;
    #pragma unroll
    for (int i = 0; i < THREADS / 32; i++) d += s[i];   // broadcast, conflict-free

    // gate = softmax max-prob = sigmoid(|d|); path 0 iff d >= 0 (argmax tie -> 0)
    const float g = 1.0f / (1.0f + __expf(-fabsf(d)));
    const bool  path0 = (d >= 0.0f);

    const float4 sv   = make_float4(v.x * g, v.y * g, v.z * g, v.w * g);
    const float4 zero = make_float4(0.f, 0.f, 0.f, 0.f);

    const size_t row4  = (size_t)n * (DHID / 4) + t;   // float4 index
    const size_t sect4 = (size_t)N_TOK * (DHID / 4);
    float4* o = reinterpret_cast<float4*>(out);

    // Plain STG.128 (streaming hints measured negative).
    o[row4]             = path0 ? sv   : zero;   // x0
    o[sect4 + row4]     = path0 ? zero : sv;     // x1
    o[2 * sect4 + row4] = sv;                    // xc
}

extern "C" void kernel_launch(void* const* d_in, const int* in_sizes, int n_in,
                              void* d_out, int out_size) {
    const float* x = (const float*)d_in[0];   // [N, D] float32
    const float* W = (const float*)d_in[1];   // [D, 2] float32
    float* out = (float*)d_out;               // [3, N, D] float32

    router_kernel<<<N_TOK, THREADS>>>(x, W, out);
}